// round 3
// baseline (speedup 1.0000x reference)
#include <cuda_runtime.h>

// GRU: B=4096, T=512, I=32, H=64. out = final hidden (B, H) fp32.
// One persistent kernel, step loop inside. 128 CTAs x 128 threads; CTA owns 32
// batch rows, warp owns 8, lane owns adjacent output pair j={2c,2c+1}.
// GEMM path: packed fma.rn.f32x2 (FFMA2). Weights read as LDS.64 pairs;
// A operands (h, x) stored DUPLICATED in smem so a ulonglong2 broadcast load
// yields packed operands with zero MOV overhead.

#define THREADS      128
#define ROWS_PER_CTA 32
#define RPW          8     // rows per warp
#define I_DIM        32
#define H_DIM        64
#define G_DIM        192   // 3*H
#define S_DUP        68    // dup-A row stride in floats (272B, 16B-aligned)

#define WS_FLOATS   (96 * G_DIM)          // 18432
#define HD_FLOATS   (H_DIM * S_DUP)       // 4352
#define XD_FLOATS   (I_DIM * S_DUP)       // 2176
#define SMEM_BYTES  ((WS_FLOATS + HD_FLOATS + XD_FLOATS) * 4)

typedef unsigned long long u64;

__device__ __forceinline__ void fma2(u64& d, u64 a, u64 b) {
    asm volatile("fma.rn.f32x2 %0, %1, %2, %0;" : "+l"(d) : "l"(a), "l"(b));
}
__device__ __forceinline__ float2 upk(u64 v) {
    float2 f;
    asm("mov.b64 {%0, %1}, %2;" : "=f"(f.x), "=f"(f.y) : "l"(v));
    return f;
}
__device__ __forceinline__ float tanh_hw(float x) {     // r,z gates (2nd-order err)
    float y;
    asm("tanh.approx.f32 %0, %1;" : "=f"(y) : "f"(x));
    return y;
}
__device__ __forceinline__ float sig_hw(float x) {
    return fmaf(tanh_hw(0.5f * x), 0.5f, 0.5f);
}
__device__ __forceinline__ float tanh_acc(float x) {    // n gate (1st-order err)
    return __fdividef(2.0f, 1.0f + __expf(-2.0f * x)) - 1.0f;
}

__global__ void __launch_bounds__(THREADS, 1)
gru_fwd_kernel(const float* __restrict__ seq,
               const float* __restrict__ W_ih,
               const float* __restrict__ W_hh,
               const float* __restrict__ b_ih,
               const float* __restrict__ b_hh,
               float* __restrict__ out,
               int B, int T)
{
    extern __shared__ float sm[];
    float* Ws = sm;                       // Ws[k][g], k<64: W_hh^T, k>=64: W_ih^T
    float* HD = sm + WS_FLOATS;           // HD[k][2*row] duplicated h
    float* XD = HD + HD_FLOATS;           // XD[k][2*row] duplicated x_t

    const int tid = threadIdx.x;
    const int w   = tid >> 5;             // warp 0..3
    const int c   = tid & 31;
    const int bb  = blockIdx.x * ROWS_PER_CTA;
    const int r0  = w * RPW;
    const int j0  = 2 * c;                // this lane's output pair {j0, j0+1}

    // ---- one-time weight transpose into smem ----
    for (int idx = tid; idx < G_DIM * H_DIM; idx += THREADS) {
        int g = idx / H_DIM, k = idx % H_DIM;
        Ws[k * G_DIM + g] = W_hh[idx];
    }
    for (int idx = tid; idx < G_DIM * I_DIM; idx += THREADS) {
        int g = idx / I_DIM, i = idx % I_DIM;
        Ws[(H_DIM + i) * G_DIM + g] = W_ih[idx];
    }
    for (int idx = tid; idx < HD_FLOATS; idx += THREADS) HD[idx] = 0.0f;

    // ---- biases for this lane's pair ----
    float bR0  = b_ih[j0]       + b_hh[j0];
    float bR1  = b_ih[j0 + 1]   + b_hh[j0 + 1];
    float bZ0  = b_ih[64 + j0]  + b_hh[64 + j0];
    float bZ1  = b_ih[65 + j0]  + b_hh[65 + j0];
    float bIN0 = b_ih[128 + j0],      bIN1 = b_ih[129 + j0];
    float bHN0 = b_hh[128 + j0],      bHN1 = b_hh[129 + j0];

    // ---- x loader role: 4 threads per batch row, 8 cols each ----
    const int xrow = tid >> 2;            // 0..31
    const int xq   = (tid & 3) * 8;       // col base 0,8,16,24
    const float* xptr = seq + (size_t)(bb + xrow) * T * I_DIM + xq;

    float hreg[RPW][2];
    #pragma unroll
    for (int i = 0; i < RPW; ++i) { hreg[i][0] = 0.0f; hreg[i][1] = 0.0f; }

    // stage x(0) duplicated
    {
        float4 a = *reinterpret_cast<const float4*>(xptr);
        float4 b = *reinterpret_cast<const float4*>(xptr + 4);
        float v[8] = {a.x, a.y, a.z, a.w, b.x, b.y, b.z, b.w};
        #pragma unroll
        for (int i = 0; i < 8; ++i)
            *reinterpret_cast<float2*>(&XD[(xq + i) * S_DUP + 2 * xrow]) =
                make_float2(v[i], v[i]);
    }
    __syncthreads();

    for (int t = 0; t < T; ++t) {
        // prefetch x(t+1) under the GEMM
        float4 xa = make_float4(0.f, 0.f, 0.f, 0.f), xb = xa;
        if (t + 1 < T) {
            const float* p = xptr + (size_t)(t + 1) * I_DIM;
            xa = *reinterpret_cast<const float4*>(p);
            xb = *reinterpret_cast<const float4*>(p + 4);
        }

        u64 aR[RPW], aZ[RPW], aN[RPW], aX[RPW];
        #pragma unroll
        for (int i = 0; i < RPW; ++i) { aR[i] = 0; aZ[i] = 0; aN[i] = 0; aX[i] = 0; }

        // ---- recurrent GEMM: k over H ----
        #pragma unroll 4
        for (int k = 0; k < H_DIM; ++k) {
            const float* hk = &HD[k * S_DUP + 2 * r0];
            ulonglong2 A0 = *reinterpret_cast<const ulonglong2*>(hk);       // rows r0,r0+1
            ulonglong2 A1 = *reinterpret_cast<const ulonglong2*>(hk + 4);   // r0+2,r0+3
            ulonglong2 A2 = *reinterpret_cast<const ulonglong2*>(hk + 8);
            ulonglong2 A3 = *reinterpret_cast<const ulonglong2*>(hk + 12);
            const float* wk = &Ws[k * G_DIM + j0];
            u64 wr = *reinterpret_cast<const u64*>(wk);
            u64 wz = *reinterpret_cast<const u64*>(wk + 64);
            u64 wn = *reinterpret_cast<const u64*>(wk + 128);
            fma2(aR[0], A0.x, wr); fma2(aR[1], A0.y, wr);
            fma2(aR[2], A1.x, wr); fma2(aR[3], A1.y, wr);
            fma2(aR[4], A2.x, wr); fma2(aR[5], A2.y, wr);
            fma2(aR[6], A3.x, wr); fma2(aR[7], A3.y, wr);
            fma2(aZ[0], A0.x, wz); fma2(aZ[1], A0.y, wz);
            fma2(aZ[2], A1.x, wz); fma2(aZ[3], A1.y, wz);
            fma2(aZ[4], A2.x, wz); fma2(aZ[5], A2.y, wz);
            fma2(aZ[6], A3.x, wz); fma2(aZ[7], A3.y, wz);
            fma2(aN[0], A0.x, wn); fma2(aN[1], A0.y, wn);
            fma2(aN[2], A1.x, wn); fma2(aN[3], A1.y, wn);
            fma2(aN[4], A2.x, wn); fma2(aN[5], A2.y, wn);
            fma2(aN[6], A3.x, wn); fma2(aN[7], A3.y, wn);
        }
        // ---- input GEMM: k over I ----
        #pragma unroll 4
        for (int k = 0; k < I_DIM; ++k) {
            const float* xk = &XD[k * S_DUP + 2 * r0];
            ulonglong2 A0 = *reinterpret_cast<const ulonglong2*>(xk);
            ulonglong2 A1 = *reinterpret_cast<const ulonglong2*>(xk + 4);
            ulonglong2 A2 = *reinterpret_cast<const ulonglong2*>(xk + 8);
            ulonglong2 A3 = *reinterpret_cast<const ulonglong2*>(xk + 12);
            const float* wk = &Ws[(H_DIM + k) * G_DIM + j0];
            u64 wr = *reinterpret_cast<const u64*>(wk);
            u64 wz = *reinterpret_cast<const u64*>(wk + 64);
            u64 wn = *reinterpret_cast<const u64*>(wk + 128);
            fma2(aR[0], A0.x, wr); fma2(aR[1], A0.y, wr);
            fma2(aR[2], A1.x, wr); fma2(aR[3], A1.y, wr);
            fma2(aR[4], A2.x, wr); fma2(aR[5], A2.y, wr);
            fma2(aR[6], A3.x, wr); fma2(aR[7], A3.y, wr);
            fma2(aZ[0], A0.x, wz); fma2(aZ[1], A0.y, wz);
            fma2(aZ[2], A1.x, wz); fma2(aZ[3], A1.y, wz);
            fma2(aZ[4], A2.x, wz); fma2(aZ[5], A2.y, wz);
            fma2(aZ[6], A3.x, wz); fma2(aZ[7], A3.y, wz);
            fma2(aX[0], A0.x, wn); fma2(aX[1], A0.y, wn);
            fma2(aX[2], A1.x, wn); fma2(aX[3], A1.y, wn);
            fma2(aX[4], A2.x, wn); fma2(aX[5], A2.y, wn);
            fma2(aX[6], A3.x, wn); fma2(aX[7], A3.y, wn);
        }

        __syncthreads();   // all smem reads for step t complete

        // stage x(t+1) duplicated
        if (t + 1 < T) {
            float v[8] = {xa.x, xa.y, xa.z, xa.w, xb.x, xb.y, xb.z, xb.w};
            #pragma unroll
            for (int i = 0; i < 8; ++i)
                *reinterpret_cast<float2*>(&XD[(xq + i) * S_DUP + 2 * xrow]) =
                    make_float2(v[i], v[i]);
        }

        // ---- gate epilogue + h writeback (duplicated) ----
        #pragma unroll
        for (int row = 0; row < RPW; ++row) {
            float2 uR = upk(aR[row]);
            float2 uZ = upk(aZ[row]);
            float2 uH = upk(aN[row]);
            float2 uX = upk(aX[row]);
            float r0g = sig_hw(uR.x + bR0);
            float z0g = sig_hw(uZ.x + bZ0);
            float n0  = tanh_acc(uX.x + bIN0 + r0g * (uH.x + bHN0));
            float h0  = n0 + z0g * (hreg[row][0] - n0);
            float r1g = sig_hw(uR.y + bR1);
            float z1g = sig_hw(uZ.y + bZ1);
            float n1  = tanh_acc(uX.y + bIN1 + r1g * (uH.y + bHN1));
            float h1  = n1 + z1g * (hreg[row][1] - n1);
            hreg[row][0] = h0;
            hreg[row][1] = h1;
            int gr = r0 + row;
            *reinterpret_cast<float2*>(&HD[j0 * S_DUP + 2 * gr]) = make_float2(h0, h0);
            *reinterpret_cast<float2*>(&HD[(j0 + 1) * S_DUP + 2 * gr]) = make_float2(h1, h1);
        }
        __syncthreads();   // HD/XD ready for step t+1
    }

    // ---- final output ----
    #pragma unroll
    for (int row = 0; row < RPW; ++row) {
        int b = bb + r0 + row;
        if (b < B)
            *reinterpret_cast<float2*>(&out[(size_t)b * H_DIM + j0]) =
                make_float2(hreg[row][0], hreg[row][1]);
    }
}

extern "C" void kernel_launch(void* const* d_in, const int* in_sizes, int n_in,
                              void* d_out, int out_size) {
    const float* seq  = (const float*)d_in[0];
    const float* W_ih = (const float*)d_in[1];
    const float* W_hh = (const float*)d_in[2];
    const float* b_ih = (const float*)d_in[3];
    const float* b_hh = (const float*)d_in[4];
    float* out = (float*)d_out;

    const int B = out_size / H_DIM;              // 4096
    const int T = in_sizes[0] / (B * I_DIM);     // 512

    cudaFuncSetAttribute(gru_fwd_kernel,
                         cudaFuncAttributeMaxDynamicSharedMemorySize, SMEM_BYTES);

    const int grid = (B + ROWS_PER_CTA - 1) / ROWS_PER_CTA;  // 128
    gru_fwd_kernel<<<grid, THREADS, SMEM_BYTES>>>(seq, W_ih, W_hh, b_ih, b_hh,
                                                  out, B, T);
}